// round 15
// baseline (speedup 1.0000x reference)
#include <cuda_runtime.h>
#include <cstdint>
#include <cstddef>

#define CC  128
#define MT  128
#define NTH 256

#define ABUF 18432u
#define OFB1 55296u
#define OFB2 73728u
#define SMEM_BYTES 110592u

__device__ float g_agg[40000 * CC];
__device__ float g_w1e[CC * 3 * CC];
__device__ float g_w2e[CC * CC];
__device__ float g_w1n[CC * 2 * CC];
__device__ float g_w2n[CC * CC];

struct RoleP {
    const float *seg0, *seg1, *seg2;
    const int   *idx0, *idx1, *aggidx;
    const float *W1, *W2, *B1, *B2, *G, *BN, *resid;
    float *agg, *out;
    int M, SEGS, EDGE;
};

__device__ __forceinline__ uint32_t rna(float x) {
    uint32_t u; asm("cvt.rna.tf32.f32 %0, %1;" : "=r"(u) : "f"(x)); return u;
}
__device__ __forceinline__ uint32_t su32(const void* p) {
    return (uint32_t)__cvta_generic_to_shared(p);
}
__device__ __forceinline__ void mma_t(float* c, const uint32_t* a, const uint32_t* b) {
    asm volatile(
        "mma.sync.aligned.m16n8k8.row.col.f32.tf32.tf32.f32 "
        "{%0,%1,%2,%3}, {%4,%5,%6,%7}, {%8,%9}, {%0,%1,%2,%3};"
        : "+f"(c[0]), "+f"(c[1]), "+f"(c[2]), "+f"(c[3])
        : "r"(a[0]), "r"(a[1]), "r"(a[2]), "r"(a[3]), "r"(b[0]), "r"(b[1]));
}
__device__ __forceinline__ void ldsm4(uint32_t addr, uint32_t* r) {
    asm volatile("ldmatrix.sync.aligned.m8n8.x4.shared.b16 {%0,%1,%2,%3}, [%4];"
                 : "=r"(r[0]), "=r"(r[1]), "=r"(r[2]), "=r"(r[3]) : "r"(addr));
}
__device__ __forceinline__ void ldsm4_b(uint32_t addr, uint32_t* b0, uint32_t* b1) {
    // x4 over 16 consecutive n-rows: r0=b0[0], r1=b1[0], r2=b0[1], r3=b1[1]
    asm volatile("ldmatrix.sync.aligned.m8n8.x4.shared.b16 {%0,%1,%2,%3}, [%4];"
                 : "=r"(b0[0]), "=r"(b1[0]), "=r"(b0[1]), "=r"(b1[1]) : "r"(addr));
}
#define CP16(dst, src) \
    asm volatile("cp.async.cg.shared.global [%0], [%1], 16;" \
                 :: "r"(dst), "l"(src) : "memory")
#define CPCOMMIT() asm volatile("cp.async.commit_group;" ::: "memory")
#define CPWAIT0()  asm volatile("cp.async.wait_group 0;" ::: "memory")
#define CPWAIT1()  asm volatile("cp.async.wait_group 1;" ::: "memory")

__global__ __launch_bounds__(NTH, 2)
void mlp_uni(int nbSplit, RoleP RA, RoleP RB)
{
    extern __shared__ __align__(16) float smf[];
    __shared__ int srow[3][MT];
    __shared__ int saggi[MT];
    __shared__ float sB1[CC], sB2[CC], sG[CC], sBN[CC];

    const bool roleA = (blockIdx.x < (unsigned)nbSplit);
    const RoleP* P = roleA ? &RA : &RB;
    const int tileIdx = roleA ? blockIdx.x : (blockIdx.x - nbSplit);

    const int tid  = threadIdx.x;
    const int wid  = tid >> 5;
    const int lane = tid & 31;
    const int wm   = wid & 1;
    const int wn   = wid >> 1;
    const int tile0 = tileIdx * MT;
    const int M    = P->M;
    const int SEGS = P->SEGS;
    const int EDGE = P->EDGE;
    const int K1 = SEGS * CC;
    const int r4 = lane >> 2;
    const int c4 = lane & 3;
    const int m2 = tid >> 1;
    const int h2 = tid & 1;
    const uint32_t sb = su32(smf);

    const uint32_t stDst = sb + (uint32_t)(m2 * 144 + h2 * 64);
    // A frags: x4 over 16 m-rows
    const uint32_t aBase  = sb + (uint32_t)((wm * 64 + (lane & 15)) * 144 + ((lane >> 4) << 4));
    // B frags: x4 over 16 n-rows (na pairs)
    const uint32_t bBase  = sb + OFB1 + (uint32_t)((wn * 32 + (lane & 15)) * 144 + ((lane >> 4) << 4));
    const uint32_t hBase  = sb + (uint32_t)((wm * 64 + (lane & 15)) * 528 + ((lane >> 4) << 4));
    const uint32_t b2Base = sb + OFB2 + (uint32_t)((wn * 32 + (lane & 15)) * 144 + ((lane >> 4) << 4));

    if (tid < MT) {
        int r = tile0 + tid;
        int rr = (r < M) ? r : (M - 1);
        srow[0][tid] = P->idx0 ? P->idx0[rr] : rr;
        srow[1][tid] = P->idx1 ? P->idx1[rr] : rr;
        srow[2][tid] = rr;
        if (EDGE) saggi[tid] = P->aggidx[rr];
        sB1[tid] = P->B1[tid]; sB2[tid] = P->B2[tid];
        sG[tid]  = P->G[tid];  sBN[tid] = P->BN[tid];
    }

    float acc[4][4][4];
#pragma unroll
    for (int i = 0; i < 4; i++)
#pragma unroll
        for (int j = 0; j < 4; j++)
#pragma unroll
            for (int k = 0; k < 4; k++) acc[i][j][k] = 0.f;

    __syncthreads();

    const float* pA0 = P->seg0 + (size_t)srow[0][m2] * CC + h2 * 16;
    const float* pA1 = P->seg1 + (size_t)srow[1][m2] * CC + h2 * 16;
    const float* pA2 = P->seg2 + (size_t)srow[2][m2] * CC + h2 * 16;
    const float* pW1 = P->W1 + (size_t)m2 * K1 + h2 * 16;
    const float* pW2 = P->W2 + (size_t)m2 * CC + h2 * 16;

    auto issue1 = [&](int c) {
        const int k0  = c * 32;
        const int sg  = c >> 2;
        const int off = k0 & 127;
        const float* pA = ((sg == 0) ? pA0 : ((sg == 1) ? pA1 : pA2)) + off;
        uint32_t dA = stDst + (uint32_t)(c % 3) * ABUF;
        CP16(dA, pA); CP16(dA + 16, pA + 4); CP16(dA + 32, pA + 8); CP16(dA + 48, pA + 12);
        const float* pB = pW1 + k0;
        uint32_t dB = stDst + OFB1 + (uint32_t)(c % 3) * ABUF;
        CP16(dB, pB); CP16(dB + 16, pB + 4); CP16(dB + 32, pB + 8); CP16(dB + 48, pB + 12);
        CPCOMMIT();
    };

    // ============ GEMM1: [128, SEGS*128] @ W1, K32, depth-2 pipeline ======
    const int NC1 = SEGS * 4;
    issue1(0);
    issue1(1);
#pragma unroll 1
    for (int c = 0; c < NC1; ++c) {
        if (c + 1 < NC1) { CPWAIT1(); } else { CPWAIT0(); }
        __syncthreads();
        if (c + 2 < NC1) issue1(c + 2);
        const uint32_t par = (uint32_t)(c % 3) * ABUF;
#pragma unroll
        for (int ks = 0; ks < 4; ++ks) {
            uint32_t a[4][4], b[4][2];
            ldsm4_b(bBase + par + (uint32_t)(ks * 32),        b[0], b[1]);
            ldsm4_b(bBase + par + (uint32_t)(2304 + ks * 32), b[2], b[3]);
#pragma unroll
            for (int ma = 0; ma < 4; ++ma)
                ldsm4(aBase + par + (uint32_t)(ma * 2304 + ks * 32), a[ma]);
            // A raw f32 bits (HW tf32 truncation); weights RNA'd in setup.
#pragma unroll
            for (int ma = 0; ma < 4; ++ma)
#pragma unroll
                for (int na = 0; na < 4; ++na) mma_t(acc[ma][na], a[ma], b[na]);
        }
    }
    __syncthreads();

    // issue GEMM2 W2 chunk 0 (covered by hidden-store work)
    {
        uint32_t dB = stDst + OFB2;
        CP16(dB, pW2); CP16(dB + 16, pW2 + 4); CP16(dB + 32, pW2 + 8); CP16(dB + 48, pW2 + 12);
        CPCOMMIT();
    }

    // ====== hidden: bias + SiLU, rna, store Hs[m][k] (528B stride) ========
    {
#pragma unroll
        for (int ma = 0; ma < 4; ++ma)
#pragma unroll
            for (int rh = 0; rh < 2; ++rh) {
                const int row = wm * 64 + ma * 16 + rh * 8 + r4;
#pragma unroll
                for (int na = 0; na < 4; ++na) {
                    const int col = wn * 32 + na * 8 + c4 * 2;
                    float x0 = acc[ma][na][rh * 2]     + sB1[col];
                    float x1 = acc[ma][na][rh * 2 + 1] + sB1[col + 1];
                    x0 = x0 / (1.f + __expf(-x0));
                    x1 = x1 / (1.f + __expf(-x1));
                    *(uint2*)(smf + row * 132 + col) = make_uint2(rna(x0), rna(x1));
                    acc[ma][na][rh * 2] = 0.f; acc[ma][na][rh * 2 + 1] = 0.f;
                }
            }
    }
    CPWAIT0();
    __syncthreads();

    // ============ GEMM2: hidden [128,128] @ W2, K32, double buffer ========
#pragma unroll 1
    for (int c = 0; c < 4; ++c) {
        if (c + 1 < 4) {
            const float* pB = pW2 + (c + 1) * 32;
            uint32_t dB = stDst + OFB2 + (uint32_t)((c + 1) & 1) * ABUF;
            CP16(dB, pB); CP16(dB + 16, pB + 4); CP16(dB + 32, pB + 8); CP16(dB + 48, pB + 12);
            CPCOMMIT();
        }
        const uint32_t par = (uint32_t)(c & 1) * ABUF;
#pragma unroll
        for (int ks = 0; ks < 4; ++ks) {
            uint32_t a[4][4], b[4][2];
            ldsm4_b(b2Base + par + (uint32_t)(ks * 32),        b[0], b[1]);
            ldsm4_b(b2Base + par + (uint32_t)(2304 + ks * 32), b[2], b[3]);
#pragma unroll
            for (int ma = 0; ma < 4; ++ma)
                ldsm4(hBase + (uint32_t)(ma * 8448 + c * 128 + ks * 32), a[ma]);
#pragma unroll
            for (int ma = 0; ma < 4; ++ma)
#pragma unroll
                for (int na = 0; na < 4; ++na) mma_t(acc[ma][na], a[ma], b[na]);
        }
        if (c + 1 < 4) { CPWAIT0(); __syncthreads(); }
    }

    // ============ epilogue: bias + LayerNorm (+resid / +scatter) ==========
    float2* sLN = (float2*)((char*)smf + OFB2);
    {
#pragma unroll
        for (int ma = 0; ma < 4; ++ma)
#pragma unroll
            for (int rh = 0; rh < 2; ++rh) {
                const int rloc = wm * 64 + ma * 16 + rh * 8 + r4;
                float s = 0.f, ss = 0.f;
#pragma unroll
                for (int na = 0; na < 4; ++na) {
                    const int col = wn * 32 + na * 8 + c4 * 2;
                    float y0 = acc[ma][na][rh * 2]     + sB2[col];
                    float y1 = acc[ma][na][rh * 2 + 1] + sB2[col + 1];
                    s += y0 + y1; ss += y0 * y0 + y1 * y1;
                }
                s  += __shfl_xor_sync(0xffffffffu, s, 1);
                ss += __shfl_xor_sync(0xffffffffu, ss, 1);
                s  += __shfl_xor_sync(0xffffffffu, s, 2);
                ss += __shfl_xor_sync(0xffffffffu, ss, 2);
                if (c4 == 0) sLN[rloc * 4 + wn] = make_float2(s, ss);
            }
        __syncthreads();

#pragma unroll
        for (int ma = 0; ma < 4; ++ma)
#pragma unroll
            for (int rh = 0; rh < 2; ++rh) {
                const int rloc = wm * 64 + ma * 16 + rh * 8 + r4;
                const int row  = tile0 + rloc;
                float2 p0 = sLN[rloc * 4 + 0], p1 = sLN[rloc * 4 + 1];
                float2 p2 = sLN[rloc * 4 + 2], p3 = sLN[rloc * 4 + 3];
                const float s  = p0.x + p1.x + p2.x + p3.x;
                const float ss = p0.y + p1.y + p2.y + p3.y;
                const float mu  = s * (1.f / 128.f);
                const float var = ss * (1.f / 128.f) - mu * mu;
                const float rs  = rsqrtf(var + 1e-5f);
                if (row < M) {
                    const int d = EDGE ? saggi[rloc] : 0;
#pragma unroll
                    for (int na = 0; na < 4; ++na) {
                        const int col = wn * 32 + na * 8 + c4 * 2;
                        float y0 = acc[ma][na][rh * 2]     + sB2[col];
                        float y1 = acc[ma][na][rh * 2 + 1] + sB2[col + 1];
                        float v0 = (y0 - mu) * rs * sG[col]     + sBN[col];
                        float v1 = (y1 - mu) * rs * sG[col + 1] + sBN[col + 1];
                        if (!EDGE) {
                            float2 rv = *(const float2*)(P->resid + (size_t)row * CC + col);
                            v0 += rv.x; v1 += rv.y;
                        }
                        *(float2*)(P->out + (size_t)row * CC + col) = make_float2(v0, v1);
                        if (EDGE) {
                            float* ap = P->agg + (size_t)d * CC + col;
                            asm volatile("red.global.add.v2.f32 [%0], {%1,%2};"
                                         :: "l"(ap), "f"(v0), "f"(v1) : "memory");
                        }
                    }
                }
            }
    }
}

__global__ void setup_kernel(const float* __restrict__ ew1, const float* __restrict__ ew2,
                             const float* __restrict__ nw1, const float* __restrict__ nw2,
                             int n4)
{
    const int gid = blockIdx.x * blockDim.x + threadIdx.x;
    if (gid < n4) ((float4*)g_agg)[gid] = make_float4(0.f, 0.f, 0.f, 0.f);
    if (gid < 7 * CC * CC) {
        int i = gid;
        if (i < 3 * CC * CC) {
            int k = i / CC, n = i % CC;
            g_w1e[n * 3 * CC + k] = __uint_as_float(rna(ew1[i]));
        } else if (i < 4 * CC * CC) {
            int j = i - 3 * CC * CC; int k = j / CC, n = j % CC;
            g_w2e[n * CC + k] = __uint_as_float(rna(ew2[j]));
        } else if (i < 6 * CC * CC) {
            int j = i - 4 * CC * CC; int k = j / CC, n = j % CC;
            g_w1n[n * 2 * CC + k] = __uint_as_float(rna(nw1[j]));
        } else {
            int j = i - 6 * CC * CC; int k = j / CC, n = j % CC;
            g_w2n[n * CC + k] = __uint_as_float(rna(nw2[j]));
        }
    }
}

extern "C" void kernel_launch(void* const* d_in, const int* in_sizes, int n_in,
                              void* d_out, int out_size)
{
    const float* x_src     = (const float*)d_in[0];
    const float* x_dst     = (const float*)d_in[1];
    const float* edge_attr = (const float*)d_in[2];
    const int*   edge_idx  = (const int*)d_in[3];
    const float* eb1 = (const float*)d_in[5];
    const float* eb2 = (const float*)d_in[7];
    const float* eg  = (const float*)d_in[8];
    const float* ebn = (const float*)d_in[9];
    const float* nb1 = (const float*)d_in[11];
    const float* nb2 = (const float*)d_in[13];
    const float* ng  = (const float*)d_in[14];
    const float* nbn = (const float*)d_in[15];

    const int n_src   = in_sizes[0] / CC;
    const int n_dst   = in_sizes[1] / CC;
    const int n_edges = in_sizes[2] / CC;

    const int* src_idx = edge_idx;
    const int* dst_idx = edge_idx + n_edges;

    float* out_src  = (float*)d_out;
    float* out_dst  = out_src + (size_t)n_src * CC;
    float* out_edge = out_dst + (size_t)n_dst * CC;

    float *agg, *w1e, *w2e, *w1n, *w2n;
    cudaGetSymbolAddress((void**)&agg, g_agg);
    cudaGetSymbolAddress((void**)&w1e, g_w1e);
    cudaGetSymbolAddress((void**)&w2e, g_w2e);
    cudaGetSymbolAddress((void**)&w1n, g_w1n);
    cudaGetSymbolAddress((void**)&w2n, g_w2n);

    cudaFuncSetAttribute(mlp_uni,
                         cudaFuncAttributeMaxDynamicSharedMemorySize, SMEM_BYTES);

    {
        int n4 = (n_dst * CC) / 4;
        int nthreads = n4 > 7 * CC * CC ? n4 : 7 * CC * CC;
        setup_kernel<<<(nthreads + 255) / 256, 256>>>(
            (const float*)d_in[4], (const float*)d_in[6],
            (const float*)d_in[10], (const float*)d_in[12], n4);
    }

    RoleP edgeR, srcR, dstR;
    edgeR.seg0 = x_dst;  edgeR.idx0 = dst_idx; edgeR.seg1 = x_src; edgeR.idx1 = src_idx;
    edgeR.seg2 = edge_attr; edgeR.aggidx = dst_idx;
    edgeR.W1 = w1e; edgeR.W2 = w2e; edgeR.B1 = eb1; edgeR.B2 = eb2;
    edgeR.G = eg; edgeR.BN = ebn; edgeR.resid = x_dst;
    edgeR.agg = agg; edgeR.out = out_edge;
    edgeR.M = n_edges; edgeR.SEGS = 3; edgeR.EDGE = 1;

    srcR.seg0 = x_src; srcR.idx0 = nullptr; srcR.seg1 = x_src; srcR.idx1 = nullptr;
    srcR.seg2 = x_src; srcR.aggidx = dst_idx;
    srcR.W1 = w1n; srcR.W2 = w2n; srcR.B1 = nb1; srcR.B2 = nb2;
    srcR.G = ng; srcR.BN = nbn; srcR.resid = x_src;
    srcR.agg = agg; srcR.out = out_src;
    srcR.M = n_src; srcR.SEGS = 2; srcR.EDGE = 0;

    dstR.seg0 = x_dst; dstR.idx0 = nullptr; dstR.seg1 = agg; dstR.idx1 = nullptr;
    dstR.seg2 = x_dst; dstR.aggidx = dst_idx;
    dstR.W1 = w1n; dstR.W2 = w2n; dstR.B1 = nb1; dstR.B2 = nb2;
    dstR.G = ng; dstR.BN = nbn; dstR.resid = x_dst;
    dstR.agg = agg; dstR.out = out_dst;
    dstR.M = n_dst; dstR.SEGS = 2; dstR.EDGE = 0;

    const int nbE = (n_edges + MT - 1) / MT;
    const int nbS = (n_src + MT - 1) / MT;
    const int nbD = (n_dst + MT - 1) / MT;

    mlp_uni<<<nbE + nbS, NTH, SMEM_BYTES>>>(nbE, edgeR, srcR);
    mlp_uni<<<nbD, NTH, SMEM_BYTES>>>(nbD, dstR, dstR);
}

// round 17
// speedup vs baseline: 1.0453x; 1.0453x over previous
#include <cuda_runtime.h>
#include <cstdint>
#include <cstddef>

#define CC  128
#define MT  128
#define NTH 256

#define ABUF 18432u
#define OFB1 55296u
#define OFB2 73728u
#define SMEM_BYTES 110592u

__device__ float g_agg[40000 * CC];
__device__ float g_w1e[CC * 3 * CC];
__device__ float g_w2e[CC * CC];
__device__ float g_w1n[CC * 2 * CC];
__device__ float g_w2n[CC * CC];

struct RoleP {
    const float *seg0, *seg1, *seg2;
    const int   *idx0, *idx1, *aggidx;
    const float *W1, *W2, *B1, *B2, *G, *BN, *resid;
    float *agg, *out;
    int M, SEGS, EDGE;
};

__device__ __forceinline__ uint32_t rna(float x) {
    uint32_t u; asm("cvt.rna.tf32.f32 %0, %1;" : "=r"(u) : "f"(x)); return u;
}
__device__ __forceinline__ uint32_t su32(const void* p) {
    return (uint32_t)__cvta_generic_to_shared(p);
}
__device__ __forceinline__ void mma_t(float* c, const uint32_t* a, const uint32_t* b) {
    asm volatile(
        "mma.sync.aligned.m16n8k8.row.col.f32.tf32.tf32.f32 "
        "{%0,%1,%2,%3}, {%4,%5,%6,%7}, {%8,%9}, {%0,%1,%2,%3};"
        : "+f"(c[0]), "+f"(c[1]), "+f"(c[2]), "+f"(c[3])
        : "r"(a[0]), "r"(a[1]), "r"(a[2]), "r"(a[3]), "r"(b[0]), "r"(b[1]));
}
__device__ __forceinline__ void ldsm4(uint32_t addr, uint32_t* r) {
    asm volatile("ldmatrix.sync.aligned.m8n8.x4.shared.b16 {%0,%1,%2,%3}, [%4];"
                 : "=r"(r[0]), "=r"(r[1]), "=r"(r[2]), "=r"(r[3]) : "r"(addr));
}
__device__ __forceinline__ void ldsm2(uint32_t addr, uint32_t* r) {
    asm volatile("ldmatrix.sync.aligned.m8n8.x2.shared.b16 {%0,%1}, [%2];"
                 : "=r"(r[0]), "=r"(r[1]) : "r"(addr));
}
#define CP16(dst, src) \
    asm volatile("cp.async.cg.shared.global [%0], [%1], 16;" \
                 :: "r"(dst), "l"(src) : "memory")
#define CPCOMMIT() asm volatile("cp.async.commit_group;" ::: "memory")
#define CPWAIT0()  asm volatile("cp.async.wait_group 0;" ::: "memory")
#define CPWAIT1()  asm volatile("cp.async.wait_group 1;" ::: "memory")

__global__ __launch_bounds__(NTH, 2)
void mlp_uni(int nbSplit, RoleP RA, RoleP RB)
{
    extern __shared__ __align__(16) float smf[];
    __shared__ int srow[3][MT];
    __shared__ int saggi[MT];
    __shared__ float sB1[CC], sB2[CC], sG[CC], sBN[CC];

    const bool roleA = (blockIdx.x < (unsigned)nbSplit);
    const RoleP* P = roleA ? &RA : &RB;
    const int tileIdx = roleA ? blockIdx.x : (blockIdx.x - nbSplit);

    const int tid  = threadIdx.x;
    const int wid  = tid >> 5;
    const int lane = tid & 31;
    const int wm   = wid & 1;
    const int wn   = wid >> 1;
    const int tile0 = tileIdx * MT;
    const int M    = P->M;
    const int SEGS = P->SEGS;
    const int EDGE = P->EDGE;
    const int K1 = SEGS * CC;
    const int r4 = lane >> 2;
    const int c4 = lane & 3;
    const int m2 = tid >> 1;
    const int h2 = tid & 1;
    const uint32_t sb = su32(smf);

    const uint32_t stDst = sb + (uint32_t)(m2 * 144 + h2 * 64);
    const uint32_t aBase  = sb + (uint32_t)((wm * 64 + (lane & 15)) * 144 + ((lane >> 4) << 4));
    const uint32_t bBase  = sb + OFB1 + (uint32_t)((wn * 32 + (lane & 7)) * 144 + ((lane & 8) << 1));
    const uint32_t hBase  = sb + (uint32_t)((wm * 64 + (lane & 15)) * 528 + ((lane >> 4) << 4));
    const uint32_t b2Base = sb + OFB2 + (uint32_t)((wn * 32 + (lane & 7)) * 144 + ((lane & 8) << 1));

    if (tid < MT) {
        int r = tile0 + tid;
        int rr = (r < M) ? r : (M - 1);
        srow[0][tid] = P->idx0 ? P->idx0[rr] : rr;
        srow[1][tid] = P->idx1 ? P->idx1[rr] : rr;
        srow[2][tid] = rr;
        if (EDGE) saggi[tid] = P->aggidx[rr];
        sB1[tid] = P->B1[tid]; sB2[tid] = P->B2[tid];
        sG[tid]  = P->G[tid];  sBN[tid] = P->BN[tid];
    }

    float acc[4][4][4];
#pragma unroll
    for (int i = 0; i < 4; i++)
#pragma unroll
        for (int j = 0; j < 4; j++)
#pragma unroll
            for (int k = 0; k < 4; k++) acc[i][j][k] = 0.f;

    __syncthreads();

    const float* pA0 = P->seg0 + (size_t)srow[0][m2] * CC + h2 * 16;
    const float* pA1 = P->seg1 + (size_t)srow[1][m2] * CC + h2 * 16;
    const float* pA2 = P->seg2 + (size_t)srow[2][m2] * CC + h2 * 16;
    const float* pW1 = P->W1 + (size_t)m2 * K1 + h2 * 16;
    const float* pW2 = P->W2 + (size_t)m2 * CC + h2 * 16;

    auto issue1 = [&](int c) {
        const int k0  = c * 32;
        const int sg  = c >> 2;
        const int off = k0 & 127;
        const float* pA = ((sg == 0) ? pA0 : ((sg == 1) ? pA1 : pA2)) + off;
        uint32_t dA = stDst + (uint32_t)(c % 3) * ABUF;
        CP16(dA, pA); CP16(dA + 16, pA + 4); CP16(dA + 32, pA + 8); CP16(dA + 48, pA + 12);
        const float* pB = pW1 + k0;
        uint32_t dB = stDst + OFB1 + (uint32_t)(c % 3) * ABUF;
        CP16(dB, pB); CP16(dB + 16, pB + 4); CP16(dB + 32, pB + 8); CP16(dB + 48, pB + 12);
        CPCOMMIT();
    };

    // ============ GEMM1: [128, SEGS*128] @ W1, K32, depth-2 pipeline ======
    const int NC1 = SEGS * 4;
    issue1(0);
    issue1(1);
#pragma unroll 1
    for (int c = 0; c < NC1; ++c) {
        if (c + 1 < NC1) { CPWAIT1(); } else { CPWAIT0(); }
        __syncthreads();
        if (c + 2 < NC1) issue1(c + 2);
        const uint32_t par = (uint32_t)(c % 3) * ABUF;
#pragma unroll
        for (int ks = 0; ks < 4; ++ks) {
            uint32_t a[4][4], b[4][2];
#pragma unroll
            for (int na = 0; na < 4; ++na)
                ldsm2(bBase + par + (uint32_t)(na * 1152 + ks * 32), b[na]);
#pragma unroll
            for (int ma = 0; ma < 4; ++ma)
                ldsm4(aBase + par + (uint32_t)(ma * 2304 + ks * 32), a[ma]);
            // A fed as raw f32 bits (HW tf32 truncation); weights RNA'd in setup,
            // hidden RNA'd at store.
#pragma unroll
            for (int ma = 0; ma < 4; ++ma)
#pragma unroll
                for (int na = 0; na < 4; ++na) mma_t(acc[ma][na], a[ma], b[na]);
        }
    }
    __syncthreads();

    // issue GEMM2 W2 chunk 0 (covered by hidden-store work)
    {
        uint32_t dB = stDst + OFB2;
        CP16(dB, pW2); CP16(dB + 16, pW2 + 4); CP16(dB + 32, pW2 + 8); CP16(dB + 48, pW2 + 12);
        CPCOMMIT();
    }

    // ====== hidden: bias + SiLU, rna, store Hs[m][k] (528B stride) ========
    {
#pragma unroll
        for (int ma = 0; ma < 4; ++ma)
#pragma unroll
            for (int rh = 0; rh < 2; ++rh) {
                const int row = wm * 64 + ma * 16 + rh * 8 + r4;
#pragma unroll
                for (int na = 0; na < 4; ++na) {
                    const int col = wn * 32 + na * 8 + c4 * 2;
                    float x0 = acc[ma][na][rh * 2]     + sB1[col];
                    float x1 = acc[ma][na][rh * 2 + 1] + sB1[col + 1];
                    x0 = x0 / (1.f + __expf(-x0));
                    x1 = x1 / (1.f + __expf(-x1));
                    *(uint2*)(smf + row * 132 + col) = make_uint2(rna(x0), rna(x1));
                    acc[ma][na][rh * 2] = 0.f; acc[ma][na][rh * 2 + 1] = 0.f;
                }
            }
    }
    CPWAIT0();
    __syncthreads();

    // ============ GEMM2: hidden [128,128] @ W2, K32, double buffer ========
#pragma unroll 1
    for (int c = 0; c < 4; ++c) {
        if (c + 1 < 4) {
            const float* pB = pW2 + (c + 1) * 32;
            uint32_t dB = stDst + OFB2 + (uint32_t)((c + 1) & 1) * ABUF;
            CP16(dB, pB); CP16(dB + 16, pB + 4); CP16(dB + 32, pB + 8); CP16(dB + 48, pB + 12);
            CPCOMMIT();
        }
        const uint32_t par = (uint32_t)(c & 1) * ABUF;
#pragma unroll
        for (int ks = 0; ks < 4; ++ks) {
            uint32_t a[4][4], b[4][2];
#pragma unroll
            for (int na = 0; na < 4; ++na)
                ldsm2(b2Base + par + (uint32_t)(na * 1152 + ks * 32), b[na]);
#pragma unroll
            for (int ma = 0; ma < 4; ++ma)
                ldsm4(hBase + (uint32_t)(ma * 8448 + c * 128 + ks * 32), a[ma]);
#pragma unroll
            for (int ma = 0; ma < 4; ++ma)
#pragma unroll
                for (int na = 0; na < 4; ++na) mma_t(acc[ma][na], a[ma], b[na]);
        }
        if (c + 1 < 4) { CPWAIT0(); __syncthreads(); }
    }

    // ============ epilogue: bias + LayerNorm (+resid / +scatter) ==========
    float2* sLN = (float2*)((char*)smf + OFB2);
    {
#pragma unroll
        for (int ma = 0; ma < 4; ++ma)
#pragma unroll
            for (int rh = 0; rh < 2; ++rh) {
                const int rloc = wm * 64 + ma * 16 + rh * 8 + r4;
                float s = 0.f, ss = 0.f;
#pragma unroll
                for (int na = 0; na < 4; ++na) {
                    const int col = wn * 32 + na * 8 + c4 * 2;
                    float y0 = acc[ma][na][rh * 2]     + sB2[col];
                    float y1 = acc[ma][na][rh * 2 + 1] + sB2[col + 1];
                    s += y0 + y1; ss += y0 * y0 + y1 * y1;
                }
                s  += __shfl_xor_sync(0xffffffffu, s, 1);
                ss += __shfl_xor_sync(0xffffffffu, ss, 1);
                s  += __shfl_xor_sync(0xffffffffu, s, 2);
                ss += __shfl_xor_sync(0xffffffffu, ss, 2);
                if (c4 == 0) sLN[rloc * 4 + wn] = make_float2(s, ss);
            }
        __syncthreads();

#pragma unroll
        for (int ma = 0; ma < 4; ++ma)
#pragma unroll
            for (int rh = 0; rh < 2; ++rh) {
                const int rloc = wm * 64 + ma * 16 + rh * 8 + r4;
                const int row  = tile0 + rloc;
                float2 p0 = sLN[rloc * 4 + 0], p1 = sLN[rloc * 4 + 1];
                float2 p2 = sLN[rloc * 4 + 2], p3 = sLN[rloc * 4 + 3];
                const float s  = p0.x + p1.x + p2.x + p3.x;
                const float ss = p0.y + p1.y + p2.y + p3.y;
                const float mu  = s * (1.f / 128.f);
                const float var = ss * (1.f / 128.f) - mu * mu;
                const float rs  = rsqrtf(var + 1e-5f);
                if (row < M) {
                    const int d = EDGE ? saggi[rloc] : 0;
#pragma unroll
                    for (int na = 0; na < 4; ++na) {
                        const int col = wn * 32 + na * 8 + c4 * 2;
                        float y0 = acc[ma][na][rh * 2]     + sB2[col];
                        float y1 = acc[ma][na][rh * 2 + 1] + sB2[col + 1];
                        float v0 = (y0 - mu) * rs * sG[col]     + sBN[col];
                        float v1 = (y1 - mu) * rs * sG[col + 1] + sBN[col + 1];
                        if (!EDGE) {
                            float2 rv = *(const float2*)(P->resid + (size_t)row * CC + col);
                            v0 += rv.x; v1 += rv.y;
                        }
                        *(float2*)(P->out + (size_t)row * CC + col) = make_float2(v0, v1);
                        if (EDGE) {
                            float* ap = P->agg + (size_t)d * CC + col;
                            asm volatile("red.global.add.v2.f32 [%0], {%1,%2};"
                                         :: "l"(ap), "f"(v0), "f"(v1) : "memory");
                        }
                    }
                }
            }
    }
}

__global__ void setup_kernel(const float* __restrict__ ew1, const float* __restrict__ ew2,
                             const float* __restrict__ nw1, const float* __restrict__ nw2,
                             int n4)
{
    const int gid = blockIdx.x * blockDim.x + threadIdx.x;
    if (gid < n4) ((float4*)g_agg)[gid] = make_float4(0.f, 0.f, 0.f, 0.f);
    if (gid < 7 * CC * CC) {
        int i = gid;
        if (i < 3 * CC * CC) {
            int k = i / CC, n = i % CC;
            g_w1e[n * 3 * CC + k] = __uint_as_float(rna(ew1[i]));
        } else if (i < 4 * CC * CC) {
            int j = i - 3 * CC * CC; int k = j / CC, n = j % CC;
            g_w2e[n * CC + k] = __uint_as_float(rna(ew2[j]));
        } else if (i < 6 * CC * CC) {
            int j = i - 4 * CC * CC; int k = j / CC, n = j % CC;
            g_w1n[n * 2 * CC + k] = __uint_as_float(rna(nw1[j]));
        } else {
            int j = i - 6 * CC * CC; int k = j / CC, n = j % CC;
            g_w2n[n * CC + k] = __uint_as_float(rna(nw2[j]));
        }
    }
}

extern "C" void kernel_launch(void* const* d_in, const int* in_sizes, int n_in,
                              void* d_out, int out_size)
{
    const float* x_src     = (const float*)d_in[0];
    const float* x_dst     = (const float*)d_in[1];
    const float* edge_attr = (const float*)d_in[2];
    const int*   edge_idx  = (const int*)d_in[3];
    const float* eb1 = (const float*)d_in[5];
    const float* eb2 = (const float*)d_in[7];
    const float* eg  = (const float*)d_in[8];
    const float* ebn = (const float*)d_in[9];
    const float* nb1 = (const float*)d_in[11];
    const float* nb2 = (const float*)d_in[13];
    const float* ng  = (const float*)d_in[14];
    const float* nbn = (const float*)d_in[15];

    const int n_src   = in_sizes[0] / CC;
    const int n_dst   = in_sizes[1] / CC;
    const int n_edges = in_sizes[2] / CC;

    const int* src_idx = edge_idx;
    const int* dst_idx = edge_idx + n_edges;

    float* out_src  = (float*)d_out;
    float* out_dst  = out_src + (size_t)n_src * CC;
    float* out_edge = out_dst + (size_t)n_dst * CC;

    float *agg, *w1e, *w2e, *w1n, *w2n;
    cudaGetSymbolAddress((void**)&agg, g_agg);
    cudaGetSymbolAddress((void**)&w1e, g_w1e);
    cudaGetSymbolAddress((void**)&w2e, g_w2e);
    cudaGetSymbolAddress((void**)&w1n, g_w1n);
    cudaGetSymbolAddress((void**)&w2n, g_w2n);

    cudaFuncSetAttribute(mlp_uni,
                         cudaFuncAttributeMaxDynamicSharedMemorySize, SMEM_BYTES);

    {
        int n4 = (n_dst * CC) / 4;
        int nthreads = n4 > 7 * CC * CC ? n4 : 7 * CC * CC;
        setup_kernel<<<(nthreads + 255) / 256, 256>>>(
            (const float*)d_in[4], (const float*)d_in[6],
            (const float*)d_in[10], (const float*)d_in[12], n4);
    }

    RoleP edgeR, srcR, dstR;
    edgeR.seg0 = x_dst;  edgeR.idx0 = dst_idx; edgeR.seg1 = x_src; edgeR.idx1 = src_idx;
    edgeR.seg2 = edge_attr; edgeR.aggidx = dst_idx;
    edgeR.W1 = w1e; edgeR.W2 = w2e; edgeR.B1 = eb1; edgeR.B2 = eb2;
    edgeR.G = eg; edgeR.BN = ebn; edgeR.resid = x_dst;
    edgeR.agg = agg; edgeR.out = out_edge;
    edgeR.M = n_edges; edgeR.SEGS = 3; edgeR.EDGE = 1;

    srcR.seg0 = x_src; srcR.idx0 = nullptr; srcR.seg1 = x_src; srcR.idx1 = nullptr;
    srcR.seg2 = x_src; srcR.aggidx = dst_idx;
    srcR.W1 = w1n; srcR.W2 = w2n; srcR.B1 = nb1; srcR.B2 = nb2;
    srcR.G = ng; srcR.BN = nbn; srcR.resid = x_src;
    srcR.agg = agg; srcR.out = out_src;
    srcR.M = n_src; srcR.SEGS = 2; srcR.EDGE = 0;

    dstR.seg0 = x_dst; dstR.idx0 = nullptr; dstR.seg1 = agg; dstR.idx1 = nullptr;
    dstR.seg2 = x_dst; dstR.aggidx = dst_idx;
    dstR.W1 = w1n; dstR.W2 = w2n; dstR.B1 = nb1; dstR.B2 = nb2;
    dstR.G = ng; dstR.BN = nbn; dstR.resid = x_dst;
    dstR.agg = agg; dstR.out = out_dst;
    dstR.M = n_dst; dstR.SEGS = 2; dstR.EDGE = 0;

    const int nbE = (n_edges + MT - 1) / MT;
    const int nbS = (n_src + MT - 1) / MT;
    const int nbD = (n_dst + MT - 1) / MT;

    mlp_uni<<<nbE + nbS, NTH, SMEM_BYTES>>>(nbE, edgeR, srcR);
    mlp_uni<<<nbD, NTH, SMEM_BYTES>>>(nbD, dstR, dstR);
}